// round 1
// baseline (speedup 1.0000x reference)
#include <cuda_runtime.h>
#include <cuda_bf16.h>
#include <cfloat>

// Problem constants
#define B_   32
#define N_   512
#define D_   791
#define H_   7
#define DK_  113
#define M_   (B_ * N_)     // 16384
#define MAXP 64

// ---------------- scratch (device globals; no allocation allowed) -------------
__device__ float g_q[M_ * D_];
__device__ float g_k[M_ * D_];
__device__ float g_h[M_ * D_];
__device__ float g_attn[B_ * N_ * N_];
__device__ int   g_pos[B_ * MAXP * 2];
__device__ int   g_cnt[B_];

// ---------------- Kernel 1: SGEMM with optional bias --------------------------
// C[M,N] = A[M,K] @ W[K,N] (+ bias[N]).  BM=BN=128, BK=8, 256 threads, 8x8/thread.
__global__ __launch_bounds__(256) void sgemm_bias_kernel(
    const float* __restrict__ A, const float* __restrict__ W,
    const float* __restrict__ bias, float* __restrict__ C,
    int M, int N, int K)
{
    __shared__ float As[8][128];
    __shared__ float Bs[8][128];

    const int tid = threadIdx.x;
    const int bm = blockIdx.y * 128;
    const int bn = blockIdx.x * 128;
    const int ty = tid >> 4;          // 0..15
    const int tx = tid & 15;          // 0..15

    float acc[8][8];
    #pragma unroll
    for (int i = 0; i < 8; i++)
        #pragma unroll
        for (int j = 0; j < 8; j++) acc[i][j] = 0.f;

    const int a_row = tid >> 1;            // 0..127
    const int a_col = (tid & 1) * 4;       // 0 or 4
    const int b_row = tid >> 5;            // 0..7
    const int b_col = (tid & 31) * 4;      // 0..124

    const float* Arow = A + (size_t)(bm + a_row) * K;

    for (int k0 = 0; k0 < K; k0 += 8) {
        #pragma unroll
        for (int i = 0; i < 4; i++) {
            int kk = k0 + a_col + i;
            As[a_col + i][a_row] = (kk < K) ? Arow[kk] : 0.f;
        }
        {
            int kk = k0 + b_row;
            const float* Wrow = W + (size_t)kk * N;
            #pragma unroll
            for (int i = 0; i < 4; i++) {
                int n = bn + b_col + i;
                Bs[b_row][b_col + i] = (kk < K && n < N) ? Wrow[n] : 0.f;
            }
        }
        __syncthreads();

        #pragma unroll
        for (int kk = 0; kk < 8; kk++) {
            float a[8], b[8];
            #pragma unroll
            for (int i = 0; i < 8; i++) a[i] = As[kk][ty * 8 + i];
            #pragma unroll
            for (int j = 0; j < 8; j++) b[j] = Bs[kk][tx * 8 + j];
            #pragma unroll
            for (int i = 0; i < 8; i++)
                #pragma unroll
                for (int j = 0; j < 8; j++)
                    acc[i][j] = fmaf(a[i], b[j], acc[i][j]);
        }
        __syncthreads();
    }

    #pragma unroll
    for (int i = 0; i < 8; i++) {
        int m = bm + ty * 8 + i;           // M divisible by 128 here
        float* Crow = C + (size_t)m * N;
        #pragma unroll
        for (int j = 0; j < 8; j++) {
            int n = bn + tx * 8 + j;
            if (n < N) {
                float v = acc[i][j];
                if (bias) v += __ldg(&bias[n]);
                Crow[n] = v;
            }
        }
    }
}

// ---------------- Kernel 2: attention -> attn[B,N,N] --------------------------
// Per block: batch b, 32 query rows. For each head: compute 32x512 scores
// (tiled over m in 128s), softmax per row, accumulate across heads in smem.
#define ATTN_SMEM_FLOATS (DK_*32 + DK_*128 + 32*N_ + 32*N_)   // 50848 floats = 203392 B

__global__ __launch_bounds__(256) void attn_kernel(
    const float* __restrict__ q, const float* __restrict__ k,
    float* __restrict__ attn)
{
    extern __shared__ float sm[];
    float* q_s = sm;                      // [DK][32]  k-major
    float* k_s = q_s + DK_ * 32;          // [DK][128] k-major
    float* S   = k_s + DK_ * 128;         // [32][512]
    float* acc = S + 32 * N_;             // [32][512]

    const int tid = threadIdx.x;
    const int b  = blockIdx.y;
    const int n0 = blockIdx.x * 32;
    const float scale = rsqrtf((float)DK_);

    for (int i = tid; i < 32 * N_; i += 256) acc[i] = 0.f;

    const int wid  = tid >> 5;            // 0..7
    const int lane = tid & 31;
    const int ty   = tid >> 5;            // n-group 0..7 -> rows ty*4..ty*4+3
    const int tx   = tid & 31;            // m-group 0..31 -> cols tx*4..tx*4+3

    for (int h = 0; h < H_; h++) {
        const int kb = h * DK_;
        // load q slice [32 rows][113] transposed into q_s (coalesced on k)
        for (int i = tid; i < DK_ * 32; i += 256) {
            int n = i / DK_, kk = i % DK_;
            q_s[kk * 32 + n] = q[((size_t)(b * N_ + n0 + n)) * D_ + kb + kk];
        }
        for (int mt = 0; mt < 4; mt++) {
            const int m0 = mt * 128;
            __syncthreads();   // prev k_s consumed; q_s visible (mt==0)
            for (int i = tid; i < DK_ * 128; i += 256) {
                int m = i / DK_, kk = i % DK_;
                k_s[kk * 128 + m] = k[((size_t)(b * N_ + m0 + m)) * D_ + kb + kk];
            }
            __syncthreads();

            float r[4][4];
            #pragma unroll
            for (int i = 0; i < 4; i++)
                #pragma unroll
                for (int j = 0; j < 4; j++) r[i][j] = 0.f;

            for (int kk = 0; kk < DK_; kk++) {
                float4 a = *reinterpret_cast<const float4*>(&q_s[kk * 32 + ty * 4]);
                float4 bb = *reinterpret_cast<const float4*>(&k_s[kk * 128 + tx * 4]);
                float av[4] = {a.x, a.y, a.z, a.w};
                float bv[4] = {bb.x, bb.y, bb.z, bb.w};
                #pragma unroll
                for (int i = 0; i < 4; i++)
                    #pragma unroll
                    for (int j = 0; j < 4; j++)
                        r[i][j] = fmaf(av[i], bv[j], r[i][j]);
            }
            #pragma unroll
            for (int i = 0; i < 4; i++)
                #pragma unroll
                for (int j = 0; j < 4; j++)
                    S[(ty * 4 + i) * N_ + m0 + tx * 4 + j] = r[i][j] * scale;
        }
        __syncthreads();   // S complete

        // softmax per row, accumulate into acc. warp w -> rows w*4..w*4+3
        for (int rr = 0; rr < 4; rr++) {
            const int n = wid * 4 + rr;
            float* Sr = S + n * N_;
            float mx = -FLT_MAX;
            for (int j = lane; j < N_; j += 32) mx = fmaxf(mx, Sr[j]);
            #pragma unroll
            for (int o = 16; o > 0; o >>= 1) mx = fmaxf(mx, __shfl_xor_sync(0xFFFFFFFFu, mx, o));
            float sum = 0.f;
            for (int j = lane; j < N_; j += 32) {
                float e = __expf(Sr[j] - mx);
                Sr[j] = e;
                sum += e;
            }
            #pragma unroll
            for (int o = 16; o > 0; o >>= 1) sum += __shfl_xor_sync(0xFFFFFFFFu, sum, o);
            float inv = __frcp_rn(sum);
            for (int j = lane; j < N_; j += 32) acc[n * N_ + j] += Sr[j] * inv;
        }
        __syncthreads();   // acc/S consumed before next head
    }

    for (int i = tid; i < 32 * N_; i += 256) {
        int n = i / N_, m = i % N_;
        attn[((size_t)b * N_ + n0 + n) * N_ + m] = acc[i];
    }
}

// ---------------- Kernel 3: per-batch top-2 threshold + positions -------------
__global__ __launch_bounds__(256) void top2_kernel(
    const float* __restrict__ attn, int* __restrict__ pos, int* __restrict__ cnt)
{
    __shared__ float v1s[256], v2s[256];
    __shared__ float s_kth;
    __shared__ int   s_cnt;

    const int b = blockIdx.x;
    const int tid = threadIdx.x;
    const float* A = attn + (size_t)b * N_ * N_;

    float v1 = -FLT_MAX, v2 = -FLT_MAX;
    for (int i = tid; i < N_ * N_; i += 256) {
        float v = A[i];
        if (v > v1) { v2 = v1; v1 = v; }
        else if (v > v2) v2 = v;
    }
    v1s[tid] = v1; v2s[tid] = v2;
    __syncthreads();
    if (tid == 0) {
        float t1 = -FLT_MAX, t2 = -FLT_MAX;
        for (int i = 0; i < 256; i++) {
            float a = v1s[i], c = v2s[i];
            if (a > t1) { t2 = t1; t1 = a; } else if (a > t2) t2 = a;
            if (c > t1) { t2 = t1; t1 = c; } else if (c > t2) t2 = c;
        }
        s_kth = t2;      // 2nd-largest (duplicates count)
        s_cnt = 0;
    }
    __syncthreads();
    const float kth = s_kth;
    const int base = b * MAXP * 2;
    for (int i = tid; i < N_ * N_; i += 256) {
        if (A[i] >= kth) {
            int idx = atomicAdd(&s_cnt, 1);
            if (idx < MAXP) {
                pos[base + idx * 2]     = i >> 9;   // row
                pos[base + idx * 2 + 1] = i & (N_ - 1); // col
            }
        }
    }
    __syncthreads();
    if (tid == 0) {
        int c = s_cnt < MAXP ? s_cnt : MAXP;
        // deterministic order: insertion sort by linear index
        for (int a2 = 1; a2 < c; a2++) {
            int ki = pos[base + a2 * 2], kj = pos[base + a2 * 2 + 1];
            int key = ki * N_ + kj;
            int p = a2 - 1;
            while (p >= 0) {
                int pi = pos[base + p * 2], pj = pos[base + p * 2 + 1];
                if (pi * N_ + pj <= key) break;
                pos[base + (p + 1) * 2] = pi;
                pos[base + (p + 1) * 2 + 1] = pj;
                p--;
            }
            pos[base + (p + 1) * 2] = ki;
            pos[base + (p + 1) * 2 + 1] = kj;
        }
        cnt[b] = c;
    }
}

// ---------------- Kernel 4: sparse adjacency apply + GC epilogue --------------
// out[b,n,:] = relu( (attn[n,n]*hid[n,:] + sum_sparse w_c*hid[col,:]) / denom + b_gc )
__global__ __launch_bounds__(256) void out_kernel(
    const float* __restrict__ attn, const float* __restrict__ hidden,
    const float* __restrict__ bgc, const int* __restrict__ pos,
    const int* __restrict__ cnt, float* __restrict__ out)
{
    const int b = blockIdx.y;
    const int n = blockIdx.x;
    const int tid = threadIdx.x;

    __shared__ int   s_nc;
    __shared__ int   s_cols[2 * MAXP];
    __shared__ float s_w[2 * MAXP];
    __shared__ float s_wd, s_inv;

    if (tid == 0) {
        const float* An = attn + ((size_t)b * N_ + n) * N_;
        const int base = b * MAXP * 2;
        int c = cnt[b];
        int nc = 0;
        float wd = An[n];
        float sum = wd;
        for (int e = 0; e < c; e++) {
            int i = pos[base + e * 2], j = pos[base + e * 2 + 1];
            if (i == n && j != n) { float w = An[j]; s_cols[nc] = j; s_w[nc] = w; sum += w; nc++; }
            if (j == n && i != n) { float w = An[i]; s_cols[nc] = i; s_w[nc] = w; sum += w; nc++; }
        }
        s_nc = nc; s_wd = wd; s_inv = 1.f / (sum + 1.f);
    }
    __syncthreads();

    const int nc = s_nc;
    const float wd = s_wd, inv = s_inv;
    const float* hn = hidden + ((size_t)b * N_ + n) * D_;
    float* on = out + ((size_t)b * N_ + n) * D_;

    for (int d = tid; d < D_; d += 256) {
        float v = wd * hn[d];
        for (int e = 0; e < nc; e++)
            v += s_w[e] * hidden[((size_t)b * N_ + s_cols[e]) * D_ + d];
        v = v * inv + __ldg(&bgc[d]);
        on[d] = fmaxf(v, 0.f);
    }
}

// ---------------- launch ------------------------------------------------------
extern "C" void kernel_launch(void* const* d_in, const int* in_sizes, int n_in,
                              void* d_out, int out_size)
{
    const float* fuse = (const float*)d_in[0];
    const float* Wq   = (const float*)d_in[1];
    const float* bq   = (const float*)d_in[2];
    const float* Wk   = (const float*)d_in[3];
    const float* bk   = (const float*)d_in[4];
    const float* Wgc  = (const float*)d_in[5];
    const float* bgc  = (const float*)d_in[6];
    float* out = (float*)d_out;

    float *q, *k, *hid, *attn;
    int *pos, *cnt;
    cudaGetSymbolAddress((void**)&q,    g_q);
    cudaGetSymbolAddress((void**)&k,    g_k);
    cudaGetSymbolAddress((void**)&hid,  g_h);
    cudaGetSymbolAddress((void**)&attn, g_attn);
    cudaGetSymbolAddress((void**)&pos,  g_pos);
    cudaGetSymbolAddress((void**)&cnt,  g_cnt);

    // 1) three projection GEMMs (hidden has NO bias — b_gc applied in epilogue)
    dim3 gg((D_ + 127) / 128, M_ / 128);
    sgemm_bias_kernel<<<gg, 256>>>(fuse, Wq,  bq,      q,   M_, D_, D_);
    sgemm_bias_kernel<<<gg, 256>>>(fuse, Wk,  bk,      k,   M_, D_, D_);
    sgemm_bias_kernel<<<gg, 256>>>(fuse, Wgc, nullptr, hid, M_, D_, D_);

    // 2) attention -> attn
    const int attn_smem = ATTN_SMEM_FLOATS * (int)sizeof(float);
    cudaFuncSetAttribute(attn_kernel, cudaFuncAttributeMaxDynamicSharedMemorySize, attn_smem);
    attn_kernel<<<dim3(N_ / 32, B_), 256, attn_smem>>>(q, k, attn);

    // 3) per-batch top-2 threshold + sparse positions
    top2_kernel<<<B_, 256>>>(attn, pos, cnt);

    // 4) sparse adjacency apply + graph-conv epilogue
    out_kernel<<<dim3(N_, B_), 256>>>(attn, hid, bgc, pos, cnt, out);
}

// round 3
// speedup vs baseline: 1.6980x; 1.6980x over previous
#include <cuda_runtime.h>
#include <cuda_fp16.h>
#include <cfloat>
#include <cstdint>

// Problem constants
#define B_   32
#define N_   512
#define D_   791
#define H_   7
#define DK_  113
#define M_   (B_ * N_)     // 16384
#define MAXP 64

// HMMA GEMM geometry
#define KP_     832          // padded K (13 * 64)
#define NCH     26           // 2 split terms * 13 chunks of K=64 halves
#define NPAD_   2432         // fused N = 3*791 = 2373 padded to 19*128
#define STAGE_B 32768        // A 128x64 fp16 (16KB) + B 128x64 fp16 (16KB)
#define GEMM_SMEM (4 * STAGE_B + 256)

// ---------------- scratch (device globals; no allocation allowed) -------------
__device__ __align__(256) __half g_Ahi[M_ * KP_];
__device__ __align__(256) __half g_Alo[M_ * KP_];
__device__ __align__(256) __half g_Bh [NPAD_ * KP_];
__device__ float g_q[M_ * D_];
__device__ float g_k[M_ * D_];
__device__ float g_h[M_ * D_];
__device__ float g_attn[B_ * N_ * N_];
__device__ int   g_pos[B_ * MAXP * 2];
__device__ int   g_cnt[B_];

// ---------------- PTX helpers --------------------------------------------------
__device__ __forceinline__ uint32_t smem_u32(const void* p) {
    uint32_t a;
    asm("{ .reg .u64 t; cvta.to.shared.u64 t, %1; cvt.u32.u64 %0, t; }" : "=r"(a) : "l"(p));
    return a;
}
__device__ __forceinline__ void ldm4(uint32_t& r0, uint32_t& r1, uint32_t& r2,
                                     uint32_t& r3, uint32_t a) {
    asm volatile("ldmatrix.sync.aligned.m8n8.x4.shared.b16 {%0,%1,%2,%3}, [%4];"
                 : "=r"(r0), "=r"(r1), "=r"(r2), "=r"(r3) : "r"(a));
}
__device__ __forceinline__ void mma16816(float* d, const uint32_t* a, const uint32_t* b) {
    asm volatile(
        "mma.sync.aligned.m16n8k16.row.col.f32.f16.f16.f32 "
        "{%0,%1,%2,%3}, {%4,%5,%6,%7}, {%8,%9}, {%0,%1,%2,%3};"
        : "+f"(d[0]), "+f"(d[1]), "+f"(d[2]), "+f"(d[3])
        : "r"(a[0]), "r"(a[1]), "r"(a[2]), "r"(a[3]), "r"(b[0]), "r"(b[1]));
}
__device__ __forceinline__ void cpa16(uint32_t dst, const void* src) {
    asm volatile("cp.async.cg.shared.global [%0], [%1], 16;" :: "r"(dst), "l"(src));
}

// ---------------- split conversions --------------------------------------------
__global__ __launch_bounds__(256) void convA_kernel(
    const float* __restrict__ fuse, __half* __restrict__ Ahi, __half* __restrict__ Alo)
{
    int idx = blockIdx.x * 256 + threadIdx.x;      // over M_*KP_
    if (idx >= M_ * KP_) return;
    int m = idx / KP_, k = idx - m * KP_;
    float x = (k < D_) ? fuse[(size_t)m * D_ + k] : 0.f;
    __half hi = __float2half_rn(x);
    float lo = x - __half2float(hi);
    Ahi[idx] = hi;
    Alo[idx] = __float2half_rn(lo);
}

__global__ __launch_bounds__(256) void convB_kernel(
    const float* __restrict__ Wq, const float* __restrict__ Wk,
    const float* __restrict__ Wgc, __half* __restrict__ Bh)
{
    int idx = blockIdx.x * 256 + threadIdx.x;      // over NPAD_*KP_
    if (idx >= NPAD_ * KP_) return;
    int n = idx / KP_, k = idx - n * KP_;
    float x = 0.f;
    if (n < 3 * D_ && k < D_) {
        const float* W;
        int col;
        if (n < D_)          { W = Wq;  col = n; }
        else if (n < 2 * D_) { W = Wk;  col = n - D_; }
        else                 { W = Wgc; col = n - 2 * D_; }
        x = __ldg(&W[(size_t)k * D_ + col]);       // B[n,k] = W[k,col]
    }
    Bh[idx] = __float2half_rn(x);
}

// ---------------- HMMA fused GEMM ----------------------------------------------
// C[16384, 2373] (q | k | hidden), K fused as (Ahi*B ; Alo*B), 26 chunks of 64.
// CTA 128x128, 8 warps (4 m x 2 n), warp tile 32x64, m16n8k16 HMMA, 4-stage cp.async.
__device__ __forceinline__ void issue_chunk(
    int cc, int tid, int m0, int nt0, uint32_t sb,
    const __half* __restrict__ Ahi, const __half* __restrict__ Alo,
    const __half* __restrict__ Bh)
{
    const int seg = (cc >= 13);
    const int kk0 = (cc - seg * 13) * 64;
    const __half* As = seg ? Alo : Ahi;
    const uint32_t st = sb + (cc & 3) * STAGE_B;
    #pragma unroll
    for (int it = 0; it < 4; it++) {               // A: 1024 x 16B
        int i = tid + it * 256;
        int r = i >> 3, u = i & 7;
        const __half* src = As + (size_t)(m0 + r) * KP_ + kk0 + u * 8;
        cpa16(st + r * 128 + (((u ^ (r & 7))) << 4), src);
    }
    #pragma unroll
    for (int it = 0; it < 4; it++) {               // B: 1024 x 16B
        int i = tid + it * 256;
        int r = i >> 3, u = i & 7;
        const __half* src = Bh + (size_t)(nt0 + r) * KP_ + kk0 + u * 8;
        cpa16(st + 16384 + r * 128 + (((u ^ (r & 7))) << 4), src);
    }
    asm volatile("cp.async.commit_group;" ::: "memory");
}

__global__ __launch_bounds__(256) void gemm_hmma_kernel(
    const __half* __restrict__ Ahi, const __half* __restrict__ Alo,
    const __half* __restrict__ Bh,
    const float* __restrict__ bq, const float* __restrict__ bk,
    float* __restrict__ q, float* __restrict__ kk, float* __restrict__ hid)
{
    extern __shared__ char smc[];
    const uint32_t sb = (smem_u32(smc) + 127) & ~127u;
    const int tid = threadIdx.x;
    const int wid = tid >> 5, lane = tid & 31;
    const int m0 = blockIdx.y * 128;
    const int nt0 = blockIdx.x * 128;

    float acc[2][8][4];
    #pragma unroll
    for (int t = 0; t < 2; t++)
        #pragma unroll
        for (int j = 0; j < 8; j++)
            #pragma unroll
            for (int e = 0; e < 4; e++) acc[t][j][e] = 0.f;

    issue_chunk(0, tid, m0, nt0, sb, Ahi, Alo, Bh);
    issue_chunk(1, tid, m0, nt0, sb, Ahi, Alo, Bh);
    issue_chunk(2, tid, m0, nt0, sb, Ahi, Alo, Bh);

    const int warp_m = wid & 3, warp_n = wid >> 2;
    const int rowinA = (lane & 7) + ((lane >> 3) & 1) * 8;   // 0..15
    const int hbA    = lane >> 4;                            // 0/1
    const int rowinB = (lane & 7) + ((lane >> 4) & 1) * 8;
    const int hbB    = (lane >> 3) & 1;

    for (int cc = 0; cc < NCH; cc++) {
        const int rem = NCH - 1 - cc;
        if (rem >= 2)      asm volatile("cp.async.wait_group 2;" ::: "memory");
        else if (rem == 1) asm volatile("cp.async.wait_group 1;" ::: "memory");
        else               asm volatile("cp.async.wait_group 0;" ::: "memory");
        __syncthreads();
        if (cc + 3 < NCH) issue_chunk(cc + 3, tid, m0, nt0, sb, Ahi, Alo, Bh);

        const uint32_t st = sb + (cc & 3) * STAGE_B;
        #pragma unroll
        for (int s = 0; s < 4; s++) {
            uint32_t a[2][4], b[8][2];
            #pragma unroll
            for (int t = 0; t < 2; t++) {
                int r = warp_m * 32 + t * 16 + rowinA;
                uint32_t ad = st + r * 128 + ((((s << 1) | hbA) ^ (r & 7)) << 4);
                ldm4(a[t][0], a[t][1], a[t][2], a[t][3], ad);
            }
            #pragma unroll
            for (int jj = 0; jj < 4; jj++) {
                int r = warp_n * 64 + jj * 16 + rowinB;
                uint32_t ad = st + 16384 + r * 128 + ((((s << 1) | hbB) ^ (r & 7)) << 4);
                ldm4(b[2 * jj][0], b[2 * jj][1], b[2 * jj + 1][0], b[2 * jj + 1][1], ad);
            }
            #pragma unroll
            for (int t = 0; t < 2; t++)
                #pragma unroll
                for (int j = 0; j < 8; j++)
                    mma16816(acc[t][j], a[t], b[j]);
        }
    }

    // epilogue: demux to q | k | hid with bias
    #pragma unroll
    for (int t = 0; t < 2; t++) {
        const int row0 = m0 + warp_m * 32 + t * 16 + (lane >> 2);
        #pragma unroll
        for (int j = 0; j < 8; j++) {
            const int col = nt0 + warp_n * 64 + j * 8 + (lane & 3) * 2;
            #pragma unroll
            for (int half = 0; half < 2; half++) {
                const int row = row0 + half * 8;
                const float v0 = acc[t][j][half * 2];
                const float v1 = acc[t][j][half * 2 + 1];
                #pragma unroll
                for (int e = 0; e < 2; e++) {
                    const int c = col + e;
                    const float v = e ? v1 : v0;
                    if (c < D_)
                        q[(size_t)row * D_ + c] = v + __ldg(&bq[c]);
                    else if (c < 2 * D_)
                        kk[(size_t)row * D_ + (c - D_)] = v + __ldg(&bk[c - D_]);
                    else if (c < 3 * D_)
                        hid[(size_t)row * D_ + (c - 2 * D_)] = v;
                }
            }
        }
    }
}

// ---------------- Kernel 2: attention -> attn[B,N,N] --------------------------
#define ATTN_SMEM_FLOATS (DK_*32 + DK_*128 + 32*N_ + 32*N_)

__global__ __launch_bounds__(256) void attn_kernel(
    const float* __restrict__ q, const float* __restrict__ k,
    float* __restrict__ attn)
{
    extern __shared__ float sm[];
    float* q_s = sm;                      // [DK][32]
    float* k_s = q_s + DK_ * 32;          // [DK][128]
    float* S   = k_s + DK_ * 128;         // [32][512]
    float* acc = S + 32 * N_;             // [32][512]

    const int tid = threadIdx.x;
    const int b  = blockIdx.y;
    const int n0 = blockIdx.x * 32;
    const float scale = rsqrtf((float)DK_);

    for (int i = tid; i < 32 * N_; i += 256) acc[i] = 0.f;

    const int wid  = tid >> 5;
    const int lane = tid & 31;
    const int ty   = tid >> 5;
    const int tx   = tid & 31;

    for (int h = 0; h < H_; h++) {
        const int kb = h * DK_;
        for (int i = tid; i < DK_ * 32; i += 256) {
            int n = i / DK_, kkx = i % DK_;
            q_s[kkx * 32 + n] = q[((size_t)(b * N_ + n0 + n)) * D_ + kb + kkx];
        }
        for (int mt = 0; mt < 4; mt++) {
            const int m0 = mt * 128;
            __syncthreads();
            for (int i = tid; i < DK_ * 128; i += 256) {
                int m = i / DK_, kkx = i % DK_;
                k_s[kkx * 128 + m] = k[((size_t)(b * N_ + m0 + m)) * D_ + kb + kkx];
            }
            __syncthreads();

            float r[4][4];
            #pragma unroll
            for (int i = 0; i < 4; i++)
                #pragma unroll
                for (int j = 0; j < 4; j++) r[i][j] = 0.f;

            for (int kkx = 0; kkx < DK_; kkx++) {
                float4 a = *reinterpret_cast<const float4*>(&q_s[kkx * 32 + ty * 4]);
                float4 bb = *reinterpret_cast<const float4*>(&k_s[kkx * 128 + tx * 4]);
                float av[4] = {a.x, a.y, a.z, a.w};
                float bv[4] = {bb.x, bb.y, bb.z, bb.w};
                #pragma unroll
                for (int i = 0; i < 4; i++)
                    #pragma unroll
                    for (int j = 0; j < 4; j++)
                        r[i][j] = fmaf(av[i], bv[j], r[i][j]);
            }
            #pragma unroll
            for (int i = 0; i < 4; i++)
                #pragma unroll
                for (int j = 0; j < 4; j++)
                    S[(ty * 4 + i) * N_ + m0 + tx * 4 + j] = r[i][j] * scale;
        }
        __syncthreads();

        for (int rr = 0; rr < 4; rr++) {
            const int n = wid * 4 + rr;
            float* Sr = S + n * N_;
            float mx = -FLT_MAX;
            for (int j = lane; j < N_; j += 32) mx = fmaxf(mx, Sr[j]);
            #pragma unroll
            for (int o = 16; o > 0; o >>= 1) mx = fmaxf(mx, __shfl_xor_sync(0xFFFFFFFFu, mx, o));
            float sum = 0.f;
            for (int j = lane; j < N_; j += 32) {
                float e = __expf(Sr[j] - mx);
                Sr[j] = e;
                sum += e;
            }
            #pragma unroll
            for (int o = 16; o > 0; o >>= 1) sum += __shfl_xor_sync(0xFFFFFFFFu, sum, o);
            float inv = __frcp_rn(sum);
            for (int j = lane; j < N_; j += 32) acc[n * N_ + j] += Sr[j] * inv;
        }
        __syncthreads();
    }

    for (int i = tid; i < 32 * N_; i += 256) {
        int n = i / N_, m = i % N_;
        attn[((size_t)b * N_ + n0 + n) * N_ + m] = acc[i];
    }
}

// ---------------- Kernel 3: per-batch top-2 threshold + positions -------------
__global__ __launch_bounds__(256) void top2_kernel(
    const float* __restrict__ attn, int* __restrict__ pos, int* __restrict__ cnt)
{
    __shared__ float v1s[256], v2s[256];
    __shared__ float s_kth;
    __shared__ int   s_cnt;

    const int b = blockIdx.x;
    const int tid = threadIdx.x;
    const float* A = attn + (size_t)b * N_ * N_;

    float v1 = -FLT_MAX, v2 = -FLT_MAX;
    for (int i = tid; i < N_ * N_; i += 256) {
        float v = A[i];
        if (v > v1) { v2 = v1; v1 = v; }
        else if (v > v2) v2 = v;
    }
    v1s[tid] = v1; v2s[tid] = v2;
    __syncthreads();
    if (tid == 0) {
        float t1 = -FLT_MAX, t2 = -FLT_MAX;
        for (int i = 0; i < 256; i++) {
            float a = v1s[i], c = v2s[i];
            if (a > t1) { t2 = t1; t1 = a; } else if (a > t2) t2 = a;
            if (c > t1) { t2 = t1; t1 = c; } else if (c > t2) t2 = c;
        }
        s_kth = t2;
        s_cnt = 0;
    }
    __syncthreads();
    const float kth = s_kth;
    const int base = b * MAXP * 2;
    for (int i = tid; i < N_ * N_; i += 256) {
        if (A[i] >= kth) {
            int idx = atomicAdd(&s_cnt, 1);
            if (idx < MAXP) {
                pos[base + idx * 2]     = i >> 9;
                pos[base + idx * 2 + 1] = i & (N_ - 1);
            }
        }
    }
    __syncthreads();
    if (tid == 0) {
        int c = s_cnt < MAXP ? s_cnt : MAXP;
        for (int a2 = 1; a2 < c; a2++) {
            int ki = pos[base + a2 * 2], kj = pos[base + a2 * 2 + 1];
            int key = ki * N_ + kj;
            int p = a2 - 1;
            while (p >= 0) {
                int pi = pos[base + p * 2], pj = pos[base + p * 2 + 1];
                if (pi * N_ + pj <= key) break;
                pos[base + (p + 1) * 2] = pi;
                pos[base + (p + 1) * 2 + 1] = pj;
                p--;
            }
            pos[base + (p + 1) * 2] = ki;
            pos[base + (p + 1) * 2 + 1] = kj;
        }
        cnt[b] = c;
    }
}

// ---------------- Kernel 4: sparse adjacency apply + GC epilogue --------------
__global__ __launch_bounds__(256) void out_kernel(
    const float* __restrict__ attn, const float* __restrict__ hidden,
    const float* __restrict__ bgc, const int* __restrict__ pos,
    const int* __restrict__ cnt, float* __restrict__ out)
{
    const int b = blockIdx.y;
    const int n = blockIdx.x;
    const int tid = threadIdx.x;

    __shared__ int   s_nc;
    __shared__ int   s_cols[2 * MAXP];
    __shared__ float s_w[2 * MAXP];
    __shared__ float s_wd, s_inv;

    if (tid == 0) {
        const float* An = attn + ((size_t)b * N_ + n) * N_;
        const int base = b * MAXP * 2;
        int c = cnt[b];
        int nc = 0;
        float wd = An[n];
        float sum = wd;
        for (int e = 0; e < c; e++) {
            int i = pos[base + e * 2], j = pos[base + e * 2 + 1];
            if (i == n && j != n) { float w = An[j]; s_cols[nc] = j; s_w[nc] = w; sum += w; nc++; }
            if (j == n && i != n) { float w = An[i]; s_cols[nc] = i; s_w[nc] = w; sum += w; nc++; }
        }
        s_nc = nc; s_wd = wd; s_inv = 1.f / (sum + 1.f);
    }
    __syncthreads();

    const int nc = s_nc;
    const float wd = s_wd, inv = s_inv;
    const float* hn = hidden + ((size_t)b * N_ + n) * D_;
    float* on = out + ((size_t)b * N_ + n) * D_;

    for (int d = tid; d < D_; d += 256) {
        float v = wd * hn[d];
        for (int e = 0; e < nc; e++)
            v += s_w[e] * hidden[((size_t)b * N_ + s_cols[e]) * D_ + d];
        v = v * inv + __ldg(&bgc[d]);
        on[d] = fmaxf(v, 0.f);
    }
}

// ---------------- launch ------------------------------------------------------
extern "C" void kernel_launch(void* const* d_in, const int* in_sizes, int n_in,
                              void* d_out, int out_size)
{
    const float* fuse = (const float*)d_in[0];
    const float* Wq   = (const float*)d_in[1];
    const float* bq   = (const float*)d_in[2];
    const float* Wk   = (const float*)d_in[3];
    const float* bk   = (const float*)d_in[4];
    const float* Wgc  = (const float*)d_in[5];
    const float* bgc  = (const float*)d_in[6];
    float* out = (float*)d_out;

    __half *Ahi, *Alo, *Bh;
    float *q, *k, *hid, *attn;
    int *pos, *cnt;
    cudaGetSymbolAddress((void**)&Ahi,  g_Ahi);
    cudaGetSymbolAddress((void**)&Alo,  g_Alo);
    cudaGetSymbolAddress((void**)&Bh,   g_Bh);
    cudaGetSymbolAddress((void**)&q,    g_q);
    cudaGetSymbolAddress((void**)&k,    g_k);
    cudaGetSymbolAddress((void**)&hid,  g_h);
    cudaGetSymbolAddress((void**)&attn, g_attn);
    cudaGetSymbolAddress((void**)&pos,  g_pos);
    cudaGetSymbolAddress((void**)&cnt,  g_cnt);

    // 0) fp16 hi/lo split of A (fuse) and fp16 fused-transposed B (Wq|Wk|Wgc)
    convA_kernel<<<(M_ * KP_ + 255) / 256, 256>>>(fuse, Ahi, Alo);
    convB_kernel<<<(NPAD_ * KP_ + 255) / 256, 256>>>(Wq, Wk, Wgc, Bh);

    // 1) fused HMMA GEMM -> q, k, hidden
    cudaFuncSetAttribute(gemm_hmma_kernel, cudaFuncAttributeMaxDynamicSharedMemorySize, GEMM_SMEM);
    gemm_hmma_kernel<<<dim3(NPAD_ / 128, M_ / 128), 256, GEMM_SMEM>>>(
        Ahi, Alo, Bh, bq, bk, q, k, hid);

    // 2) attention -> attn
    const int attn_smem = ATTN_SMEM_FLOATS * (int)sizeof(float);
    cudaFuncSetAttribute(attn_kernel, cudaFuncAttributeMaxDynamicSharedMemorySize, attn_smem);
    attn_kernel<<<dim3(N_ / 32, B_), 256, attn_smem>>>(q, k, attn);

    // 3) per-batch top-2 threshold + sparse positions
    top2_kernel<<<B_, 256>>>(attn, pos, cnt);

    // 4) sparse adjacency apply + graph-conv epilogue
    out_kernel<<<dim3(N_, B_), 256>>>(attn, hid, bgc, pos, cnt, out);
}

// round 4
// speedup vs baseline: 1.7324x; 1.0203x over previous
#include <cuda_runtime.h>
#include <cuda_fp16.h>
#include <cfloat>
#include <cstdint>

// Problem constants
#define B_   32
#define N_   512
#define D_   791
#define H_   7
#define DK_  113
#define M_   (B_ * N_)     // 16384
#define MAXP 64

// HMMA GEMM geometry: CTA 256x128, warp tile 64x64, 8 warps, 4-stage cp.async
#define KP_     832          // padded K (13 * 64)
#define NCH     26           // 2 split terms * 13 chunks of K=64
#define NPAD_   2432         // fused N = 3*791 = 2373 padded to 19*128
#define STAGE_B 49152        // A 256x64 fp16 (32KB) + B 128x64 fp16 (16KB)
#define GEMM_SMEM (4 * STAGE_B + 256)

// ---------------- scratch (device globals; no allocation allowed) -------------
__device__ __align__(256) __half g_Ahi[M_ * KP_];
__device__ __align__(256) __half g_Alo[M_ * KP_];
__device__ __align__(256) __half g_Bh [NPAD_ * KP_];
__device__ float g_q[M_ * D_];
__device__ float g_k[M_ * D_];
__device__ float g_h[M_ * D_];
__device__ float g_attn[B_ * N_ * N_];
__device__ int   g_pos[B_ * MAXP * 2];
__device__ int   g_cnt[B_];

// ---------------- PTX helpers --------------------------------------------------
__device__ __forceinline__ uint32_t smem_u32(const void* p) {
    uint32_t a;
    asm("{ .reg .u64 t; cvta.to.shared.u64 t, %1; cvt.u32.u64 %0, t; }" : "=r"(a) : "l"(p));
    return a;
}
__device__ __forceinline__ void ldm4(uint32_t& r0, uint32_t& r1, uint32_t& r2,
                                     uint32_t& r3, uint32_t a) {
    asm volatile("ldmatrix.sync.aligned.m8n8.x4.shared.b16 {%0,%1,%2,%3}, [%4];"
                 : "=r"(r0), "=r"(r1), "=r"(r2), "=r"(r3) : "r"(a));
}
__device__ __forceinline__ void mma16816(float* d, const uint32_t* a, const uint32_t* b) {
    asm volatile(
        "mma.sync.aligned.m16n8k16.row.col.f32.f16.f16.f32 "
        "{%0,%1,%2,%3}, {%4,%5,%6,%7}, {%8,%9}, {%0,%1,%2,%3};"
        : "+f"(d[0]), "+f"(d[1]), "+f"(d[2]), "+f"(d[3])
        : "r"(a[0]), "r"(a[1]), "r"(a[2]), "r"(a[3]), "r"(b[0]), "r"(b[1]));
}
__device__ __forceinline__ void cpa16(uint32_t dst, const void* src) {
    asm volatile("cp.async.cg.shared.global [%0], [%1], 16;" :: "r"(dst), "l"(src));
}

// ---------------- split conversions --------------------------------------------
__global__ __launch_bounds__(256) void convA_kernel(
    const float* __restrict__ fuse, __half* __restrict__ Ahi, __half* __restrict__ Alo)
{
    int idx = blockIdx.x * 256 + threadIdx.x;      // over M_*KP_
    if (idx >= M_ * KP_) return;
    int m = idx / KP_, k = idx - m * KP_;
    float x = (k < D_) ? fuse[(size_t)m * D_ + k] : 0.f;
    __half hi = __float2half_rn(x);
    float lo = x - __half2float(hi);
    Ahi[idx] = hi;
    Alo[idx] = __float2half_rn(lo);
}

__global__ __launch_bounds__(256) void convB_kernel(
    const float* __restrict__ Wq, const float* __restrict__ Wk,
    const float* __restrict__ Wgc, __half* __restrict__ Bh)
{
    int idx = blockIdx.x * 256 + threadIdx.x;      // over NPAD_*KP_
    if (idx >= NPAD_ * KP_) return;
    int n = idx / KP_, k = idx - n * KP_;
    float x = 0.f;
    if (n < 3 * D_ && k < D_) {
        const float* W;
        int col;
        if (n < D_)          { W = Wq;  col = n; }
        else if (n < 2 * D_) { W = Wk;  col = n - D_; }
        else                 { W = Wgc; col = n - 2 * D_; }
        x = __ldg(&W[(size_t)k * D_ + col]);       // B[n,k] = W[k,col]
    }
    Bh[idx] = __float2half_rn(x);
}

// ---------------- HMMA fused GEMM ----------------------------------------------
// C[16384, 2373] (q | k | hidden), K fused as (Ahi*B ; Alo*B), 26 chunks of 64.
// CTA 256x128, 8 warps (4 m x 2 n), warp tile 64x64, m16n8k16 HMMA, 4-stage cp.async.
__device__ __forceinline__ void issue_chunk(
    int cc, int tid, int m0, int nt0, uint32_t sb,
    const __half* __restrict__ Ahi, const __half* __restrict__ Alo,
    const __half* __restrict__ Bh)
{
    const int seg = (cc >= 13);
    const int kk0 = (cc - seg * 13) * 64;
    const __half* As = seg ? Alo : Ahi;
    const uint32_t st = sb + (cc & 3) * STAGE_B;
    #pragma unroll
    for (int it = 0; it < 8; it++) {               // A: 2048 x 16B
        int i = tid + it * 256;
        int r = i >> 3, u = i & 7;
        const __half* src = As + (size_t)(m0 + r) * KP_ + kk0 + u * 8;
        cpa16(st + r * 128 + (((u ^ (r & 7))) << 4), src);
    }
    #pragma unroll
    for (int it = 0; it < 4; it++) {               // B: 1024 x 16B
        int i = tid + it * 256;
        int r = i >> 3, u = i & 7;
        const __half* src = Bh + (size_t)(nt0 + r) * KP_ + kk0 + u * 8;
        cpa16(st + 32768 + r * 128 + (((u ^ (r & 7))) << 4), src);
    }
    asm volatile("cp.async.commit_group;" ::: "memory");
}

__global__ __launch_bounds__(256, 1) void gemm_hmma_kernel(
    const __half* __restrict__ Ahi, const __half* __restrict__ Alo,
    const __half* __restrict__ Bh,
    const float* __restrict__ bq, const float* __restrict__ bk,
    float* __restrict__ q, float* __restrict__ kk, float* __restrict__ hid)
{
    extern __shared__ char smc[];
    const uint32_t sb = (smem_u32(smc) + 127) & ~127u;
    const int tid = threadIdx.x;
    const int wid = tid >> 5, lane = tid & 31;
    const int m0 = blockIdx.y * 256;
    const int nt0 = blockIdx.x * 128;

    float acc[4][8][4];
    #pragma unroll
    for (int t = 0; t < 4; t++)
        #pragma unroll
        for (int j = 0; j < 8; j++)
            #pragma unroll
            for (int e = 0; e < 4; e++) acc[t][j][e] = 0.f;

    issue_chunk(0, tid, m0, nt0, sb, Ahi, Alo, Bh);
    issue_chunk(1, tid, m0, nt0, sb, Ahi, Alo, Bh);
    issue_chunk(2, tid, m0, nt0, sb, Ahi, Alo, Bh);

    const int warp_m = wid & 3, warp_n = wid >> 2;
    const int rowinA = (lane & 7) + ((lane >> 3) & 1) * 8;   // 0..15
    const int hbA    = lane >> 4;                            // 0/1
    const int rowinB = (lane & 7) + ((lane >> 4) & 1) * 8;
    const int hbB    = (lane >> 3) & 1;

    for (int cc = 0; cc < NCH; cc++) {
        const int rem = NCH - 1 - cc;
        if (rem >= 2)      asm volatile("cp.async.wait_group 2;" ::: "memory");
        else if (rem == 1) asm volatile("cp.async.wait_group 1;" ::: "memory");
        else               asm volatile("cp.async.wait_group 0;" ::: "memory");
        __syncthreads();
        if (cc + 3 < NCH) issue_chunk(cc + 3, tid, m0, nt0, sb, Ahi, Alo, Bh);

        const uint32_t st = sb + (cc & 3) * STAGE_B;
        #pragma unroll
        for (int s = 0; s < 4; s++) {
            uint32_t a[4][4], b[8][2];
            #pragma unroll
            for (int t = 0; t < 4; t++) {
                int r = warp_m * 64 + t * 16 + rowinA;
                uint32_t ad = st + r * 128 + ((((s << 1) | hbA) ^ (r & 7)) << 4);
                ldm4(a[t][0], a[t][1], a[t][2], a[t][3], ad);
            }
            #pragma unroll
            for (int jj = 0; jj < 4; jj++) {
                int r = warp_n * 64 + jj * 16 + rowinB;
                uint32_t ad = st + 32768 + r * 128 + ((((s << 1) | hbB) ^ (r & 7)) << 4);
                ldm4(b[2 * jj][0], b[2 * jj][1], b[2 * jj + 1][0], b[2 * jj + 1][1], ad);
            }
            #pragma unroll
            for (int t = 0; t < 4; t++)
                #pragma unroll
                for (int j = 0; j < 8; j++)
                    mma16816(acc[t][j], a[t], b[j]);
        }
    }

    // epilogue: demux to q | k | hid with bias
    #pragma unroll
    for (int t = 0; t < 4; t++) {
        const int row0 = m0 + warp_m * 64 + t * 16 + (lane >> 2);
        #pragma unroll
        for (int j = 0; j < 8; j++) {
            const int col = nt0 + warp_n * 64 + j * 8 + (lane & 3) * 2;
            #pragma unroll
            for (int half = 0; half < 2; half++) {
                const int row = row0 + half * 8;
                const float v0 = acc[t][j][half * 2];
                const float v1 = acc[t][j][half * 2 + 1];
                #pragma unroll
                for (int e = 0; e < 2; e++) {
                    const int c = col + e;
                    const float v = e ? v1 : v0;
                    if (c < D_)
                        q[(size_t)row * D_ + c] = v + __ldg(&bq[c]);
                    else if (c < 2 * D_)
                        kk[(size_t)row * D_ + (c - D_)] = v + __ldg(&bk[c - D_]);
                    else if (c < 3 * D_)
                        hid[(size_t)row * D_ + (c - 2 * D_)] = v;
                }
            }
        }
    }
}

// ---------------- Kernel 2: attention -> attn[B,N,N] --------------------------
#define ATTN_SMEM_FLOATS (DK_*32 + DK_*128 + 32*N_ + 32*N_)

__global__ __launch_bounds__(256) void attn_kernel(
    const float* __restrict__ q, const float* __restrict__ k,
    float* __restrict__ attn)
{
    extern __shared__ float sm[];
    float* q_s = sm;                      // [DK][32]
    float* k_s = q_s + DK_ * 32;          // [DK][128]
    float* S   = k_s + DK_ * 128;         // [32][512]
    float* acc = S + 32 * N_;             // [32][512]

    const int tid = threadIdx.x;
    const int b  = blockIdx.y;
    const int n0 = blockIdx.x * 32;
    const float scale = rsqrtf((float)DK_);

    for (int i = tid; i < 32 * N_; i += 256) acc[i] = 0.f;

    const int wid  = tid >> 5;
    const int lane = tid & 31;
    const int ty   = tid >> 5;
    const int tx   = tid & 31;

    for (int h = 0; h < H_; h++) {
        const int kb = h * DK_;
        for (int i = tid; i < DK_ * 32; i += 256) {
            int n = i / DK_, kkx = i % DK_;
            q_s[kkx * 32 + n] = q[((size_t)(b * N_ + n0 + n)) * D_ + kb + kkx];
        }
        for (int mt = 0; mt < 4; mt++) {
            const int m0 = mt * 128;
            __syncthreads();
            for (int i = tid; i < DK_ * 128; i += 256) {
                int m = i / DK_, kkx = i % DK_;
                k_s[kkx * 128 + m] = k[((size_t)(b * N_ + m0 + m)) * D_ + kb + kkx];
            }
            __syncthreads();

            float r[4][4];
            #pragma unroll
            for (int i = 0; i < 4; i++)
                #pragma unroll
                for (int j = 0; j < 4; j++) r[i][j] = 0.f;

            for (int kkx = 0; kkx < DK_; kkx++) {
                float4 a = *reinterpret_cast<const float4*>(&q_s[kkx * 32 + ty * 4]);
                float4 bb = *reinterpret_cast<const float4*>(&k_s[kkx * 128 + tx * 4]);
                float av[4] = {a.x, a.y, a.z, a.w};
                float bv[4] = {bb.x, bb.y, bb.z, bb.w};
                #pragma unroll
                for (int i = 0; i < 4; i++)
                    #pragma unroll
                    for (int j = 0; j < 4; j++)
                        r[i][j] = fmaf(av[i], bv[j], r[i][j]);
            }
            #pragma unroll
            for (int i = 0; i < 4; i++)
                #pragma unroll
                for (int j = 0; j < 4; j++)
                    S[(ty * 4 + i) * N_ + m0 + tx * 4 + j] = r[i][j] * scale;
        }
        __syncthreads();

        for (int rr = 0; rr < 4; rr++) {
            const int n = wid * 4 + rr;
            float* Sr = S + n * N_;
            float mx = -FLT_MAX;
            for (int j = lane; j < N_; j += 32) mx = fmaxf(mx, Sr[j]);
            #pragma unroll
            for (int o = 16; o > 0; o >>= 1) mx = fmaxf(mx, __shfl_xor_sync(0xFFFFFFFFu, mx, o));
            float sum = 0.f;
            for (int j = lane; j < N_; j += 32) {
                float e = __expf(Sr[j] - mx);
                Sr[j] = e;
                sum += e;
            }
            #pragma unroll
            for (int o = 16; o > 0; o >>= 1) sum += __shfl_xor_sync(0xFFFFFFFFu, sum, o);
            float inv = __frcp_rn(sum);
            for (int j = lane; j < N_; j += 32) acc[n * N_ + j] += Sr[j] * inv;
        }
        __syncthreads();
    }

    for (int i = tid; i < 32 * N_; i += 256) {
        int n = i / N_, m = i % N_;
        attn[((size_t)b * N_ + n0 + n) * N_ + m] = acc[i];
    }
}

// ---------------- Kernel 3: per-batch top-2 threshold + positions -------------
__global__ __launch_bounds__(256) void top2_kernel(
    const float* __restrict__ attn, int* __restrict__ pos, int* __restrict__ cnt)
{
    __shared__ float v1s[256], v2s[256];
    __shared__ float s_kth;
    __shared__ int   s_cnt;

    const int b = blockIdx.x;
    const int tid = threadIdx.x;
    const float* A = attn + (size_t)b * N_ * N_;

    float v1 = -FLT_MAX, v2 = -FLT_MAX;
    for (int i = tid; i < N_ * N_; i += 256) {
        float v = A[i];
        if (v > v1) { v2 = v1; v1 = v; }
        else if (v > v2) v2 = v;
    }
    v1s[tid] = v1; v2s[tid] = v2;
    __syncthreads();
    if (tid == 0) {
        float t1 = -FLT_MAX, t2 = -FLT_MAX;
        for (int i = 0; i < 256; i++) {
            float a = v1s[i], c = v2s[i];
            if (a > t1) { t2 = t1; t1 = a; } else if (a > t2) t2 = a;
            if (c > t1) { t2 = t1; t1 = c; } else if (c > t2) t2 = c;
        }
        s_kth = t2;
        s_cnt = 0;
    }
    __syncthreads();
    const float kth = s_kth;
    const int base = b * MAXP * 2;
    for (int i = tid; i < N_ * N_; i += 256) {
        if (A[i] >= kth) {
            int idx = atomicAdd(&s_cnt, 1);
            if (idx < MAXP) {
                pos[base + idx * 2]     = i >> 9;
                pos[base + idx * 2 + 1] = i & (N_ - 1);
            }
        }
    }
    __syncthreads();
    if (tid == 0) {
        int c = s_cnt < MAXP ? s_cnt : MAXP;
        for (int a2 = 1; a2 < c; a2++) {
            int ki = pos[base + a2 * 2], kj = pos[base + a2 * 2 + 1];
            int key = ki * N_ + kj;
            int p = a2 - 1;
            while (p >= 0) {
                int pi = pos[base + p * 2], pj = pos[base + p * 2 + 1];
                if (pi * N_ + pj <= key) break;
                pos[base + (p + 1) * 2] = pi;
                pos[base + (p + 1) * 2 + 1] = pj;
                p--;
            }
            pos[base + (p + 1) * 2] = ki;
            pos[base + (p + 1) * 2 + 1] = kj;
        }
        cnt[b] = c;
    }
}

// ---------------- Kernel 4: sparse adjacency apply + GC epilogue --------------
__global__ __launch_bounds__(256) void out_kernel(
    const float* __restrict__ attn, const float* __restrict__ hidden,
    const float* __restrict__ bgc, const int* __restrict__ pos,
    const int* __restrict__ cnt, float* __restrict__ out)
{
    const int b = blockIdx.y;
    const int n = blockIdx.x;
    const int tid = threadIdx.x;

    __shared__ int   s_nc;
    __shared__ int   s_cols[2 * MAXP];
    __shared__ float s_w[2 * MAXP];
    __shared__ float s_wd, s_inv;

    if (tid == 0) {
        const float* An = attn + ((size_t)b * N_ + n) * N_;
        const int base = b * MAXP * 2;
        int c = cnt[b];
        int nc = 0;
        float wd = An[n];
        float sum = wd;
        for (int e = 0; e < c; e++) {
            int i = pos[base + e * 2], j = pos[base + e * 2 + 1];
            if (i == n && j != n) { float w = An[j]; s_cols[nc] = j; s_w[nc] = w; sum += w; nc++; }
            if (j == n && i != n) { float w = An[i]; s_cols[nc] = i; s_w[nc] = w; sum += w; nc++; }
        }
        s_nc = nc; s_wd = wd; s_inv = 1.f / (sum + 1.f);
    }
    __syncthreads();

    const int nc = s_nc;
    const float wd = s_wd, inv = s_inv;
    const float* hn = hidden + ((size_t)b * N_ + n) * D_;
    float* on = out + ((size_t)b * N_ + n) * D_;

    for (int d = tid; d < D_; d += 256) {
        float v = wd * hn[d];
        for (int e = 0; e < nc; e++)
            v += s_w[e] * hidden[((size_t)b * N_ + s_cols[e]) * D_ + d];
        v = v * inv + __ldg(&bgc[d]);
        on[d] = fmaxf(v, 0.f);
    }
}

// ---------------- launch ------------------------------------------------------
extern "C" void kernel_launch(void* const* d_in, const int* in_sizes, int n_in,
                              void* d_out, int out_size)
{
    const float* fuse = (const float*)d_in[0];
    const float* Wq   = (const float*)d_in[1];
    const float* bq   = (const float*)d_in[2];
    const float* Wk   = (const float*)d_in[3];
    const float* bk   = (const float*)d_in[4];
    const float* Wgc  = (const float*)d_in[5];
    const float* bgc  = (const float*)d_in[6];
    float* out = (float*)d_out;

    __half *Ahi, *Alo, *Bh;
    float *q, *k, *hid, *attn;
    int *pos, *cnt;
    cudaGetSymbolAddress((void**)&Ahi,  g_Ahi);
    cudaGetSymbolAddress((void**)&Alo,  g_Alo);
    cudaGetSymbolAddress((void**)&Bh,   g_Bh);
    cudaGetSymbolAddress((void**)&q,    g_q);
    cudaGetSymbolAddress((void**)&k,    g_k);
    cudaGetSymbolAddress((void**)&hid,  g_h);
    cudaGetSymbolAddress((void**)&attn, g_attn);
    cudaGetSymbolAddress((void**)&pos,  g_pos);
    cudaGetSymbolAddress((void**)&cnt,  g_cnt);

    // 0) fp16 hi/lo split of A (fuse) and fp16 fused-transposed B (Wq|Wk|Wgc)
    convA_kernel<<<(M_ * KP_ + 255) / 256, 256>>>(fuse, Ahi, Alo);
    convB_kernel<<<(NPAD_ * KP_ + 255) / 256, 256>>>(Wq, Wk, Wgc, Bh);

    // 1) fused HMMA GEMM -> q, k, hidden
    cudaFuncSetAttribute(gemm_hmma_kernel, cudaFuncAttributeMaxDynamicSharedMemorySize, GEMM_SMEM);
    gemm_hmma_kernel<<<dim3(NPAD_ / 128, M_ / 256), 256, GEMM_SMEM>>>(
        Ahi, Alo, Bh, bq, bk, q, k, hid);

    // 2) attention -> attn
    const int attn_smem = ATTN_SMEM_FLOATS * (int)sizeof(float);
    cudaFuncSetAttribute(attn_kernel, cudaFuncAttributeMaxDynamicSharedMemorySize, attn_smem);
    attn_kernel<<<dim3(N_ / 32, B_), 256, attn_smem>>>(q, k, attn);

    // 3) per-batch top-2 threshold + sparse positions
    top2_kernel<<<B_, 256>>>(attn, pos, cnt);

    // 4) sparse adjacency apply + graph-conv epilogue
    out_kernel<<<dim3(N_, B_), 256>>>(attn, hid, bgc, pos, cnt, out);
}

// round 5
// speedup vs baseline: 4.2285x; 2.4409x over previous
#include <cuda_runtime.h>
#include <cuda_fp16.h>
#include <cfloat>
#include <cstdint>

// Problem constants
#define B_   32
#define N_   512
#define D_   791
#define H_   7
#define DK_  113
#define M_   (B_ * N_)     // 16384
#define MAXP 64

// main HMMA GEMM geometry: CTA 256x128, warp tile 64x64, 8 warps, 4-stage cp.async
#define KP_     832          // padded K (13 * 64)
#define NCH     26           // 2 split terms * 13 chunks of K=64
#define NPAD_   2432         // fused N = 3*791 = 2373 padded to 19*128
#define STAGE_B 49152        // A 256x64 fp16 (32KB) + B 128x64 fp16 (16KB)
#define GEMM_SMEM (4 * STAGE_B + 256)

// score GEMM geometry: CTA 128x128, warp tile 32x64, K=3 terms x 128 (6 chunks of 64)
#define SKP   128
#define SNCH  6
#define SSTAGE_B 32768
#define SGEMM_SMEM (4 * SSTAGE_B + 256)
#define BHN (B_ * H_ * N_)   // 114688 packed rows

// ---------------- scratch (device globals; no allocation allowed) -------------
__device__ __align__(256) __half g_Ahi[M_ * KP_];
__device__ __align__(256) __half g_Alo[M_ * KP_];
__device__ __align__(256) __half g_Bh [NPAD_ * KP_];
__device__ __align__(256) __half g_Qhi[BHN * SKP];
__device__ __align__(256) __half g_Qlo[BHN * SKP];
__device__ __align__(256) __half g_Khi[BHN * SKP];
__device__ __align__(256) __half g_Klo[BHN * SKP];
__device__ float g_S[(size_t)B_ * H_ * N_ * N_];
__device__ float g_q[M_ * D_];
__device__ float g_k[M_ * D_];
__device__ float g_h[M_ * D_];
__device__ float g_attn[B_ * N_ * N_];
__device__ int   g_pos[B_ * MAXP * 2];
__device__ int   g_cnt[B_];

// ---------------- PTX helpers --------------------------------------------------
__device__ __forceinline__ uint32_t smem_u32(const void* p) {
    uint32_t a;
    asm("{ .reg .u64 t; cvta.to.shared.u64 t, %1; cvt.u32.u64 %0, t; }" : "=r"(a) : "l"(p));
    return a;
}
__device__ __forceinline__ void ldm4(uint32_t& r0, uint32_t& r1, uint32_t& r2,
                                     uint32_t& r3, uint32_t a) {
    asm volatile("ldmatrix.sync.aligned.m8n8.x4.shared.b16 {%0,%1,%2,%3}, [%4];"
                 : "=r"(r0), "=r"(r1), "=r"(r2), "=r"(r3) : "r"(a));
}
__device__ __forceinline__ void mma16816(float* d, const uint32_t* a, const uint32_t* b) {
    asm volatile(
        "mma.sync.aligned.m16n8k16.row.col.f32.f16.f16.f32 "
        "{%0,%1,%2,%3}, {%4,%5,%6,%7}, {%8,%9}, {%0,%1,%2,%3};"
        : "+f"(d[0]), "+f"(d[1]), "+f"(d[2]), "+f"(d[3])
        : "r"(a[0]), "r"(a[1]), "r"(a[2]), "r"(a[3]), "r"(b[0]), "r"(b[1]));
}
__device__ __forceinline__ void cpa16(uint32_t dst, const void* src) {
    asm volatile("cp.async.cg.shared.global [%0], [%1], 16;" :: "r"(dst), "l"(src));
}

// ---------------- split conversions --------------------------------------------
__global__ __launch_bounds__(256) void convA_kernel(
    const float* __restrict__ fuse, __half* __restrict__ Ahi, __half* __restrict__ Alo)
{
    int idx = blockIdx.x * 256 + threadIdx.x;      // over M_*KP_
    if (idx >= M_ * KP_) return;
    int m = idx / KP_, k = idx - m * KP_;
    float x = (k < D_) ? fuse[(size_t)m * D_ + k] : 0.f;
    __half hi = __float2half_rn(x);
    float lo = x - __half2float(hi);
    Ahi[idx] = hi;
    Alo[idx] = __float2half_rn(lo);
}

__global__ __launch_bounds__(256) void convB_kernel(
    const float* __restrict__ Wq, const float* __restrict__ Wk,
    const float* __restrict__ Wgc, __half* __restrict__ Bh)
{
    int idx = blockIdx.x * 256 + threadIdx.x;      // over NPAD_*KP_
    if (idx >= NPAD_ * KP_) return;
    int n = idx / KP_, k = idx - n * KP_;
    float x = 0.f;
    if (n < 3 * D_ && k < D_) {
        const float* W;
        int col;
        if (n < D_)          { W = Wq;  col = n; }
        else if (n < 2 * D_) { W = Wk;  col = n - D_; }
        else                 { W = Wgc; col = n - 2 * D_; }
        x = __ldg(&W[(size_t)k * D_ + col]);       // B[n,k] = W[k,col]
    }
    Bh[idx] = __float2half_rn(x);
}

// ---------------- HMMA fused GEMM ----------------------------------------------
// C[16384, 2373] (q | k | hidden). N-tiles >= 1664 (pure `hidden` cols) skip the
// lo term (nch = 13 instead of 26): hidden has no selection sensitivity.
__device__ __forceinline__ void issue_chunk(
    int cc, int tid, int m0, int nt0, uint32_t sb,
    const __half* __restrict__ Ahi, const __half* __restrict__ Alo,
    const __half* __restrict__ Bh)
{
    const int seg = (cc >= 13);
    const int kk0 = (cc - seg * 13) * 64;
    const __half* As = seg ? Alo : Ahi;
    const uint32_t st = sb + (cc & 3) * STAGE_B;
    #pragma unroll
    for (int it = 0; it < 8; it++) {               // A: 2048 x 16B
        int i = tid + it * 256;
        int r = i >> 3, u = i & 7;
        const __half* src = As + (size_t)(m0 + r) * KP_ + kk0 + u * 8;
        cpa16(st + r * 128 + (((u ^ (r & 7))) << 4), src);
    }
    #pragma unroll
    for (int it = 0; it < 4; it++) {               // B: 1024 x 16B
        int i = tid + it * 256;
        int r = i >> 3, u = i & 7;
        const __half* src = Bh + (size_t)(nt0 + r) * KP_ + kk0 + u * 8;
        cpa16(st + 32768 + r * 128 + (((u ^ (r & 7))) << 4), src);
    }
    asm volatile("cp.async.commit_group;" ::: "memory");
}

__global__ __launch_bounds__(256, 1) void gemm_hmma_kernel(
    const __half* __restrict__ Ahi, const __half* __restrict__ Alo,
    const __half* __restrict__ Bh,
    const float* __restrict__ bq, const float* __restrict__ bk,
    float* __restrict__ q, float* __restrict__ kk, float* __restrict__ hid)
{
    extern __shared__ char smc[];
    const uint32_t sb = (smem_u32(smc) + 127) & ~127u;
    const int tid = threadIdx.x;
    const int wid = tid >> 5, lane = tid & 31;
    const int m0 = blockIdx.y * 256;
    const int nt0 = blockIdx.x * 128;
    const int nch = (nt0 >= 1664) ? 13 : 26;       // pure-hidden tiles: hi term only

    float acc[4][8][4];
    #pragma unroll
    for (int t = 0; t < 4; t++)
        #pragma unroll
        for (int j = 0; j < 8; j++)
            #pragma unroll
            for (int e = 0; e < 4; e++) acc[t][j][e] = 0.f;

    issue_chunk(0, tid, m0, nt0, sb, Ahi, Alo, Bh);
    issue_chunk(1, tid, m0, nt0, sb, Ahi, Alo, Bh);
    issue_chunk(2, tid, m0, nt0, sb, Ahi, Alo, Bh);

    const int warp_m = wid & 3, warp_n = wid >> 2;
    const int rowinA = (lane & 7) + ((lane >> 3) & 1) * 8;
    const int hbA    = lane >> 4;
    const int rowinB = (lane & 7) + ((lane >> 4) & 1) * 8;
    const int hbB    = (lane >> 3) & 1;

    for (int cc = 0; cc < nch; cc++) {
        const int rem = nch - 1 - cc;
        if (rem >= 2)      asm volatile("cp.async.wait_group 2;" ::: "memory");
        else if (rem == 1) asm volatile("cp.async.wait_group 1;" ::: "memory");
        else               asm volatile("cp.async.wait_group 0;" ::: "memory");
        __syncthreads();
        if (cc + 3 < nch) issue_chunk(cc + 3, tid, m0, nt0, sb, Ahi, Alo, Bh);

        const uint32_t st = sb + (cc & 3) * STAGE_B;
        #pragma unroll
        for (int s = 0; s < 4; s++) {
            uint32_t a[4][4], b[8][2];
            #pragma unroll
            for (int t = 0; t < 4; t++) {
                int r = warp_m * 64 + t * 16 + rowinA;
                uint32_t ad = st + r * 128 + ((((s << 1) | hbA) ^ (r & 7)) << 4);
                ldm4(a[t][0], a[t][1], a[t][2], a[t][3], ad);
            }
            #pragma unroll
            for (int jj = 0; jj < 4; jj++) {
                int r = warp_n * 64 + jj * 16 + rowinB;
                uint32_t ad = st + 32768 + r * 128 + ((((s << 1) | hbB) ^ (r & 7)) << 4);
                ldm4(b[2 * jj][0], b[2 * jj][1], b[2 * jj + 1][0], b[2 * jj + 1][1], ad);
            }
            #pragma unroll
            for (int t = 0; t < 4; t++)
                #pragma unroll
                for (int j = 0; j < 8; j++)
                    mma16816(acc[t][j], a[t], b[j]);
        }
    }

    // epilogue: demux to q | k | hid with bias
    #pragma unroll
    for (int t = 0; t < 4; t++) {
        const int row0 = m0 + warp_m * 64 + t * 16 + (lane >> 2);
        #pragma unroll
        for (int j = 0; j < 8; j++) {
            const int col = nt0 + warp_n * 64 + j * 8 + (lane & 3) * 2;
            #pragma unroll
            for (int half = 0; half < 2; half++) {
                const int row = row0 + half * 8;
                const float v0 = acc[t][j][half * 2];
                const float v1 = acc[t][j][half * 2 + 1];
                #pragma unroll
                for (int e = 0; e < 2; e++) {
                    const int c = col + e;
                    const float v = e ? v1 : v0;
                    if (c < D_)
                        q[(size_t)row * D_ + c] = v + __ldg(&bq[c]);
                    else if (c < 2 * D_)
                        kk[(size_t)row * D_ + (c - D_)] = v + __ldg(&bk[c - D_]);
                    else if (c < 3 * D_)
                        hid[(size_t)row * D_ + (c - 2 * D_)] = v;
                }
            }
        }
    }
}

// ---------------- pack q/k into head-padded fp16 hi/lo --------------------------
// [B,H,N,128]: dk 0..112 real, 113..127 zero. hi/lo split for both q and k.
__global__ __launch_bounds__(256) void pack_qk_kernel(
    const float* __restrict__ q, const float* __restrict__ k,
    __half* __restrict__ Qhi, __half* __restrict__ Qlo,
    __half* __restrict__ Khi, __half* __restrict__ Klo)
{
    int idx = blockIdx.x * 256 + threadIdx.x;      // over BHN*128
    if (idx >= BHN * SKP) return;
    int dk = idx & 127;
    int rest = idx >> 7;
    int n = rest & (N_ - 1);
    int bh = rest >> 9;
    int h = bh % H_, b = bh / H_;
    float qv = 0.f, kv = 0.f;
    if (dk < DK_) {
        size_t off = ((size_t)(b * N_ + n)) * D_ + h * DK_ + dk;
        qv = q[off];
        kv = k[off];
    }
    __half qh = __float2half_rn(qv);
    __half kh = __float2half_rn(kv);
    Qhi[idx] = qh;
    Qlo[idx] = __float2half_rn(qv - __half2float(qh));
    Khi[idx] = kh;
    Klo[idx] = __float2half_rn(kv - __half2float(kh));
}

// ---------------- HMMA score GEMM ------------------------------------------------
// S[bh] = (Qhi+Qlo)@Khi^T + Qhi@Klo^T, scaled by 1/sqrt(113).
// CTA 128x128 of the 512x512 output, 8 warps (4m x 2n), warp tile 32x64.
__device__ __forceinline__ void issue_chunk_s(
    int cc, int tid, int m0, int nt0, int bh, uint32_t sb,
    const __half* __restrict__ Qhi, const __half* __restrict__ Qlo,
    const __half* __restrict__ Khi, const __half* __restrict__ Klo)
{
    const int p = cc >> 1;
    const int kk0 = (cc & 1) * 64;
    const __half* As = (p == 1) ? Qlo : Qhi;
    const __half* Bs = (p == 2) ? Klo : Khi;
    const size_t base = (size_t)bh * N_ * SKP;
    const uint32_t st = sb + (cc & 3) * SSTAGE_B;
    #pragma unroll
    for (int it = 0; it < 4; it++) {               // A: 1024 x 16B
        int i = tid + it * 256;
        int r = i >> 3, u = i & 7;
        const __half* src = As + base + (size_t)(m0 + r) * SKP + kk0 + u * 8;
        cpa16(st + r * 128 + (((u ^ (r & 7))) << 4), src);
    }
    #pragma unroll
    for (int it = 0; it < 4; it++) {               // B: 1024 x 16B
        int i = tid + it * 256;
        int r = i >> 3, u = i & 7;
        const __half* src = Bs + base + (size_t)(nt0 + r) * SKP + kk0 + u * 8;
        cpa16(st + 16384 + r * 128 + (((u ^ (r & 7))) << 4), src);
    }
    asm volatile("cp.async.commit_group;" ::: "memory");
}

__global__ __launch_bounds__(256, 1) void score_hmma_kernel(
    const __half* __restrict__ Qhi, const __half* __restrict__ Qlo,
    const __half* __restrict__ Khi, const __half* __restrict__ Klo,
    float* __restrict__ S)
{
    extern __shared__ char smc[];
    const uint32_t sb = (smem_u32(smc) + 127) & ~127u;
    const int tid = threadIdx.x;
    const int wid = tid >> 5, lane = tid & 31;
    const int m0 = blockIdx.y * 128;
    const int nt0 = blockIdx.x * 128;
    const int bh = blockIdx.z;

    float acc[2][8][4];
    #pragma unroll
    for (int t = 0; t < 2; t++)
        #pragma unroll
        for (int j = 0; j < 8; j++)
            #pragma unroll
            for (int e = 0; e < 4; e++) acc[t][j][e] = 0.f;

    issue_chunk_s(0, tid, m0, nt0, bh, sb, Qhi, Qlo, Khi, Klo);
    issue_chunk_s(1, tid, m0, nt0, bh, sb, Qhi, Qlo, Khi, Klo);
    issue_chunk_s(2, tid, m0, nt0, bh, sb, Qhi, Qlo, Khi, Klo);

    const int warp_m = wid & 3, warp_n = wid >> 2;
    const int rowinA = (lane & 7) + ((lane >> 3) & 1) * 8;
    const int hbA    = lane >> 4;
    const int rowinB = (lane & 7) + ((lane >> 4) & 1) * 8;
    const int hbB    = (lane >> 3) & 1;

    for (int cc = 0; cc < SNCH; cc++) {
        const int rem = SNCH - 1 - cc;
        if (rem >= 2)      asm volatile("cp.async.wait_group 2;" ::: "memory");
        else if (rem == 1) asm volatile("cp.async.wait_group 1;" ::: "memory");
        else               asm volatile("cp.async.wait_group 0;" ::: "memory");
        __syncthreads();
        if (cc + 3 < SNCH) issue_chunk_s(cc + 3, tid, m0, nt0, bh, sb, Qhi, Qlo, Khi, Klo);

        const uint32_t st = sb + (cc & 3) * SSTAGE_B;
        #pragma unroll
        for (int s = 0; s < 4; s++) {
            uint32_t a[2][4], b[8][2];
            #pragma unroll
            for (int t = 0; t < 2; t++) {
                int r = warp_m * 32 + t * 16 + rowinA;
                uint32_t ad = st + r * 128 + ((((s << 1) | hbA) ^ (r & 7)) << 4);
                ldm4(a[t][0], a[t][1], a[t][2], a[t][3], ad);
            }
            #pragma unroll
            for (int jj = 0; jj < 4; jj++) {
                int r = warp_n * 64 + jj * 16 + rowinB;
                uint32_t ad = st + 16384 + r * 128 + ((((s << 1) | hbB) ^ (r & 7)) << 4);
                ldm4(b[2 * jj][0], b[2 * jj][1], b[2 * jj + 1][0], b[2 * jj + 1][1], ad);
            }
            #pragma unroll
            for (int t = 0; t < 2; t++)
                #pragma unroll
                for (int j = 0; j < 8; j++)
                    mma16816(acc[t][j], a[t], b[j]);
        }
    }

    const float scale = rsqrtf((float)DK_);
    float* Sb = S + (size_t)bh * N_ * N_;
    #pragma unroll
    for (int t = 0; t < 2; t++) {
        const int row0 = m0 + warp_m * 32 + t * 16 + (lane >> 2);
        #pragma unroll
        for (int j = 0; j < 8; j++) {
            const int col = nt0 + warp_n * 64 + j * 8 + (lane & 3) * 2;
            #pragma unroll
            for (int half = 0; half < 2; half++) {
                const int row = row0 + half * 8;
                Sb[(size_t)row * N_ + col]     = acc[t][j][half * 2] * scale;
                Sb[(size_t)row * N_ + col + 1] = acc[t][j][half * 2 + 1] * scale;
            }
        }
    }
}

// ---------------- softmax + head-sum -> attn -------------------------------------
// One block per query row n (16384 blocks). Warp h handles head h's 512 scores.
__global__ __launch_bounds__(256) void softmax_kernel(
    const float* __restrict__ S, float* __restrict__ attn)
{
    __shared__ float e[H_][N_];
    __shared__ float winv[H_];

    const int tid = threadIdx.x;
    const int wid = tid >> 5, lane = tid & 31;
    const int ng = blockIdx.x;                 // global row 0..16383
    const int b = ng >> 9, n = ng & (N_ - 1);

    if (wid < H_) {
        const float* Sr = S + ((size_t)(b * H_ + wid) * N_ + n) * N_;
        float mx = -FLT_MAX;
        float v[16];
        #pragma unroll
        for (int it = 0; it < 16; it++) {
            v[it] = Sr[lane + it * 32];
            mx = fmaxf(mx, v[it]);
        }
        #pragma unroll
        for (int o = 16; o > 0; o >>= 1) mx = fmaxf(mx, __shfl_xor_sync(0xFFFFFFFFu, mx, o));
        float sum = 0.f;
        #pragma unroll
        for (int it = 0; it < 16; it++) {
            float ex = __expf(v[it] - mx);
            e[wid][lane + it * 32] = ex;
            sum += ex;
        }
        #pragma unroll
        for (int o = 16; o > 0; o >>= 1) sum += __shfl_xor_sync(0xFFFFFFFFu, sum, o);
        if (lane == 0) winv[wid] = __frcp_rn(sum);
    }
    __syncthreads();

    float* an = attn + (size_t)ng * N_;
    for (int m = tid; m < N_; m += 256) {
        float a = 0.f;
        #pragma unroll
        for (int h = 0; h < H_; h++) a += e[h][m] * winv[h];
        an[m] = a;
    }
}

// ---------------- Kernel 3: per-batch top-2 threshold + positions -------------
__global__ __launch_bounds__(256) void top2_kernel(
    const float* __restrict__ attn, int* __restrict__ pos, int* __restrict__ cnt)
{
    __shared__ float v1s[256], v2s[256];
    __shared__ float s_kth;
    __shared__ int   s_cnt;

    const int b = blockIdx.x;
    const int tid = threadIdx.x;
    const float* A = attn + (size_t)b * N_ * N_;

    float v1 = -FLT_MAX, v2 = -FLT_MAX;
    for (int i = tid; i < N_ * N_; i += 256) {
        float v = A[i];
        if (v > v1) { v2 = v1; v1 = v; }
        else if (v > v2) v2 = v;
    }
    v1s[tid] = v1; v2s[tid] = v2;
    __syncthreads();
    if (tid == 0) {
        float t1 = -FLT_MAX, t2 = -FLT_MAX;
        for (int i = 0; i < 256; i++) {
            float a = v1s[i], c = v2s[i];
            if (a > t1) { t2 = t1; t1 = a; } else if (a > t2) t2 = a;
            if (c > t1) { t2 = t1; t1 = c; } else if (c > t2) t2 = c;
        }
        s_kth = t2;
        s_cnt = 0;
    }
    __syncthreads();
    const float kth = s_kth;
    const int base = b * MAXP * 2;
    for (int i = tid; i < N_ * N_; i += 256) {
        if (A[i] >= kth) {
            int idx = atomicAdd(&s_cnt, 1);
            if (idx < MAXP) {
                pos[base + idx * 2]     = i >> 9;
                pos[base + idx * 2 + 1] = i & (N_ - 1);
            }
        }
    }
    __syncthreads();
    if (tid == 0) {
        int c = s_cnt < MAXP ? s_cnt : MAXP;
        for (int a2 = 1; a2 < c; a2++) {
            int ki = pos[base + a2 * 2], kj = pos[base + a2 * 2 + 1];
            int key = ki * N_ + kj;
            int p = a2 - 1;
            while (p >= 0) {
                int pi = pos[base + p * 2], pj = pos[base + p * 2 + 1];
                if (pi * N_ + pj <= key) break;
                pos[base + (p + 1) * 2] = pi;
                pos[base + (p + 1) * 2 + 1] = pj;
                p--;
            }
            pos[base + (p + 1) * 2] = ki;
            pos[base + (p + 1) * 2 + 1] = kj;
        }
        cnt[b] = c;
    }
}

// ---------------- Kernel 4: sparse adjacency apply + GC epilogue --------------
__global__ __launch_bounds__(256) void out_kernel(
    const float* __restrict__ attn, const float* __restrict__ hidden,
    const float* __restrict__ bgc, const int* __restrict__ pos,
    const int* __restrict__ cnt, float* __restrict__ out)
{
    const int b = blockIdx.y;
    const int n = blockIdx.x;
    const int tid = threadIdx.x;

    __shared__ int   s_nc;
    __shared__ int   s_cols[2 * MAXP];
    __shared__ float s_w[2 * MAXP];
    __shared__ float s_wd, s_inv;

    if (tid == 0) {
        const float* An = attn + ((size_t)b * N_ + n) * N_;
        const int base = b * MAXP * 2;
        int c = cnt[b];
        int nc = 0;
        float wd = An[n];
        float sum = wd;
        for (int e = 0; e < c; e++) {
            int i = pos[base + e * 2], j = pos[base + e * 2 + 1];
            if (i == n && j != n) { float w = An[j]; s_cols[nc] = j; s_w[nc] = w; sum += w; nc++; }
            if (j == n && i != n) { float w = An[i]; s_cols[nc] = i; s_w[nc] = w; sum += w; nc++; }
        }
        s_nc = nc; s_wd = wd; s_inv = 1.f / (sum + 1.f);
    }
    __syncthreads();

    const int nc = s_nc;
    const float wd = s_wd, inv = s_inv;
    const float* hn = hidden + ((size_t)b * N_ + n) * D_;
    float* on = out + ((size_t)b * N_ + n) * D_;

    for (int d = tid; d < D_; d += 256) {
        float v = wd * hn[d];
        for (int e = 0; e < nc; e++)
            v += s_w[e] * hidden[((size_t)b * N_ + s_cols[e]) * D_ + d];
        v = v * inv + __ldg(&bgc[d]);
        on[d] = fmaxf(v, 0.f);
    }
}

// ---------------- launch ------------------------------------------------------
extern "C" void kernel_launch(void* const* d_in, const int* in_sizes, int n_in,
                              void* d_out, int out_size)
{
    const float* fuse = (const float*)d_in[0];
    const float* Wq   = (const float*)d_in[1];
    const float* bq   = (const float*)d_in[2];
    const float* Wk   = (const float*)d_in[3];
    const float* bk   = (const float*)d_in[4];
    const float* Wgc  = (const float*)d_in[5];
    const float* bgc  = (const float*)d_in[6];
    float* out = (float*)d_out;

    __half *Ahi, *Alo, *Bh, *Qhi, *Qlo, *Khi, *Klo;
    float *q, *k, *hid, *attn, *S;
    int *pos, *cnt;
    cudaGetSymbolAddress((void**)&Ahi,  g_Ahi);
    cudaGetSymbolAddress((void**)&Alo,  g_Alo);
    cudaGetSymbolAddress((void**)&Bh,   g_Bh);
    cudaGetSymbolAddress((void**)&Qhi,  g_Qhi);
    cudaGetSymbolAddress((void**)&Qlo,  g_Qlo);
    cudaGetSymbolAddress((void**)&Khi,  g_Khi);
    cudaGetSymbolAddress((void**)&Klo,  g_Klo);
    cudaGetSymbolAddress((void**)&S,    g_S);
    cudaGetSymbolAddress((void**)&q,    g_q);
    cudaGetSymbolAddress((void**)&k,    g_k);
    cudaGetSymbolAddress((void**)&hid,  g_h);
    cudaGetSymbolAddress((void**)&attn, g_attn);
    cudaGetSymbolAddress((void**)&pos,  g_pos);
    cudaGetSymbolAddress((void**)&cnt,  g_cnt);

    // 0) fp16 hi/lo split of A (fuse) and fp16 fused-transposed B (Wq|Wk|Wgc)
    convA_kernel<<<(M_ * KP_ + 255) / 256, 256>>>(fuse, Ahi, Alo);
    convB_kernel<<<(NPAD_ * KP_ + 255) / 256, 256>>>(Wq, Wk, Wgc, Bh);

    // 1) fused HMMA GEMM -> q, k, hidden
    cudaFuncSetAttribute(gemm_hmma_kernel, cudaFuncAttributeMaxDynamicSharedMemorySize, GEMM_SMEM);
    gemm_hmma_kernel<<<dim3(NPAD_ / 128, M_ / 256), 256, GEMM_SMEM>>>(
        Ahi, Alo, Bh, bq, bk, q, k, hid);

    // 2) pack q/k head-padded fp16 hi/lo
    pack_qk_kernel<<<(BHN * SKP + 255) / 256, 256>>>(q, k, Qhi, Qlo, Khi, Klo);

    // 3) HMMA score GEMM -> S[B,H,N,N]
    cudaFuncSetAttribute(score_hmma_kernel, cudaFuncAttributeMaxDynamicSharedMemorySize, SGEMM_SMEM);
    score_hmma_kernel<<<dim3(N_ / 128, N_ / 128, B_ * H_), 256, SGEMM_SMEM>>>(
        Qhi, Qlo, Khi, Klo, S);

    // 4) softmax + head-sum -> attn
    softmax_kernel<<<M_, 256>>>(S, attn);

    // 5) per-batch top-2 threshold + sparse positions
    top2_kernel<<<B_, 256>>>(attn, pos, cnt);

    // 6) sparse adjacency apply + graph-conv epilogue
    out_kernel<<<dim3(N_, B_), 256>>>(attn, hid, bgc, pos, cnt, out);
}